// round 4
// baseline (speedup 1.0000x reference)
#include <cuda_runtime.h>
#include <math.h>

#define NN 30000
#define NE 300000
#define HH 128
#define H3 384
#define RR 200
#define RRELU_SLOPE 0.22916666666666666f

// ---------------- scratch ----------------
__device__ unsigned char g_mask[(size_t)RR * NN];
__device__ float g_deg[NN];
__device__ float g_rel[RR * HH];
__device__ float g_relsum[RR * HH];
__device__ int   g_relcnt[RR];
__device__ float g_agg[(size_t)NN * HH];
__device__ float g_nf [(size_t)NN * HH];
__device__ float g_ef [(size_t)NE * HH];
__device__ float g_ein[(size_t)NE * HH];
__device__ float g_emsg[(size_t)NE * HH];
__device__ float g_gh [(size_t)NE * H3];     // shared GRU h-path, once per layer
__device__ float g_Wg[2 * 512 * 128];        // gate-interleaved Wih (r,z,n,0)
__device__ float g_bg[2 * 512];

// ---------------- helpers ----------------
__device__ __forceinline__ unsigned f2tf(float x) {
    unsigned r;
    asm("cvt.rna.tf32.f32 %0, %1;" : "=r"(r) : "f"(x));
    return r;
}
__device__ __forceinline__ float sig_f(float x) { return 1.0f / (1.0f + __expf(-x)); }
__device__ __forceinline__ float tanh_f(float x) { return 2.0f / (1.0f + __expf(-2.0f * x)) - 1.0f; }

#define MMA_TF32(c, a, b)                                                         \
    asm volatile(                                                                 \
        "mma.sync.aligned.m16n8k8.row.col.f32.tf32.tf32.f32 "                     \
        "{%0,%1,%2,%3}, {%4,%5,%6,%7}, {%8,%9}, {%0,%1,%2,%3};"                   \
        : "+f"(c[0]), "+f"(c[1]), "+f"(c[2]), "+f"(c[3])                          \
        : "r"(a[0]), "r"(a[1]), "r"(a[2]), "r"(a[3]), "r"(b[0]), "r"(b[1]))

// ---------------- zero / build ----------------
__global__ void k_zero_mask_deg() {
    size_t i = (size_t)blockIdx.x * blockDim.x + threadIdx.x;
    const size_t W = (size_t)RR * NN / 4;
    if (i < W) ((unsigned int*)g_mask)[i] = 0u;
    if (i < NN) g_deg[i] = 0.0f;
}

__global__ void k_zero2() {
    size_t i = (size_t)blockIdx.x * blockDim.x + threadIdx.x;
    if (i < (size_t)NN * HH) g_agg[i] = 0.0f;
    if (i < RR * HH) g_relsum[i] = 0.0f;
    if (i < RR) g_relcnt[i] = 0;
}

__global__ void k_build(const int* __restrict__ src, const int* __restrict__ dst,
                        const int* __restrict__ et) {
    int e = blockIdx.x * blockDim.x + threadIdx.x;
    if (e >= NE) return;
    int r = et[e];
    g_mask[(size_t)r * NN + src[e]] = 1;
    g_mask[(size_t)r * NN + dst[e]] = 1;
    atomicAdd(&g_deg[dst[e]], 1.0f);
}

// ---------------- GRU gi weight packing (K=128) ----------------------------
// Wg[l][4h+gate][k]: gate0=Wih[h], 1=Wih[128+h], 2=Wih[256+h], 3=zero.
__global__ void k_pack(const float* __restrict__ Wih, const float* __restrict__ bih) {
    int idx = blockIdx.x * blockDim.x + threadIdx.x;
    if (idx >= 2 * 512 * 128) return;
    int l = idx >> 16;
    int rp = (idx >> 7) & 511;
    int k = idx & 127;
    int h = rp >> 2, gate = rp & 3;
    const float* wi = Wih + (size_t)l * H3 * HH;
    float v = (gate < 3) ? wi[(gate * 128 + h) * HH + k] : 0.0f;
    g_Wg[idx] = v;
    if (k == 0)
        g_bg[l * 512 + rp] = (gate < 3) ? bih[l * H3 + gate * 128 + h] : 0.0f;
}

// ---------------- rel_emb (split 8-way) ------------------------------------
__global__ __launch_bounds__(256) void k_rel_part(const float* __restrict__ nf) {
    int r = blockIdx.x;
    int nbeg = blockIdx.y * 3750;
    int nend = nbeg + 3750; if (nend > NN) nend = NN;
    int warp = threadIdx.x >> 5, lane = threadIdx.x & 31;
    const unsigned char* mrow = g_mask + (size_t)r * NN;
    float a0 = 0.f, a1 = 0.f, a2 = 0.f, a3 = 0.f;
    int cnt = 0;
    for (int base = nbeg + warp * 32; base < nend; base += 256) {
        int n = base + lane;
        bool set = (n < nend) && mrow[n];
        unsigned ball = __ballot_sync(0xffffffffu, set);
        cnt += (int)set;
        while (ball) {
            int b = __ffs(ball) - 1;
            ball &= ball - 1;
            const float* row = nf + (size_t)(base + b) * HH;
            a0 += row[lane]; a1 += row[lane + 32];
            a2 += row[lane + 64]; a3 += row[lane + 96];
        }
    }
    __shared__ float ss[8][128];
    __shared__ int sc[8];
    #pragma unroll
    for (int off = 16; off; off >>= 1) cnt += __shfl_xor_sync(0xffffffffu, cnt, off);
    if (lane == 0) sc[warp] = cnt;
    ss[warp][lane] = a0; ss[warp][lane + 32] = a1;
    ss[warp][lane + 64] = a2; ss[warp][lane + 96] = a3;
    __syncthreads();
    if (threadIdx.x < 128) {
        float s = 0.f;
        #pragma unroll
        for (int w = 0; w < 8; w++) s += ss[w][threadIdx.x];
        atomicAdd(&g_relsum[r * HH + threadIdx.x], s);
    }
    if (threadIdx.x == 128) {
        int c = 0;
        #pragma unroll
        for (int w = 0; w < 8; w++) c += sc[w];
        atomicAdd(&g_relcnt[r], c);
    }
}

__global__ void k_rel_fin() {
    int idx = blockIdx.x * blockDim.x + threadIdx.x;
    if (idx >= RR * HH) return;
    int c = g_relcnt[idx >> 7];
    g_rel[idx] = (c > 0) ? g_relsum[idx] / (float)c : 0.0f;
}

// ---------------- TF32 TC gather-GEMM v4 -----------------------------------
// BM=BN=128, BK=32; 8 warps (4m x 2n), warp 32m x 64n.
// Smem: stride-32 words + XOR-bit2 chunk swizzle -> conflict-free LDS.128.
// k-permutation: one uint4 frag load serves two k8 MMA steps.
// mode 0: store; 1: atomicAdd g_agg[dst]; 2: node rrelu; 4: fused GRU w/ gh.
__global__ __launch_bounds__(256, 2) void k_gemm_v4(
    int M, int K, int Nout,
    const float* __restrict__ s0, const int* __restrict__ i0,
    const float* __restrict__ s1, const int* __restrict__ i1,
    const float* __restrict__ s2, const int* __restrict__ i2,
    const float* __restrict__ W, const float* __restrict__ bias,
    float* __restrict__ out, int mode, const int* __restrict__ dstIdx)
{
    __shared__ unsigned As[128 * 32];
    __shared__ unsigned Bs[128 * 32];
    __shared__ const float* rowp[128][3];

    int tid = threadIdx.x;
    int m0 = blockIdx.x * 128, n0 = blockIdx.y * 128;

    if (tid < 128) {
        int e = m0 + tid; if (e > M - 1) e = M - 1;
        rowp[tid][0] = s0 + (size_t)(i0 ? i0[e] : e) * HH;
        rowp[tid][1] = s1 ? (s1 + (size_t)(i1 ? i1[e] : e) * HH) : s0;
        rowp[tid][2] = s2 ? (s2 + (size_t)(i2 ? i2[e] : e) * HH) : s0;
    }
    __syncthreads();

    int lane = tid & 31, wid = tid >> 5;
    int wm = wid >> 1, wn = wid & 1;
    int g = lane >> 2, tg = lane & 3;
    int am = tid >> 3, aq = tid & 7;
    int swq = (aq ^ ((am & 1) << 2)) << 2;   // swizzled word offset for STS

    float acc[2][8][4];
    #pragma unroll
    for (int a = 0; a < 2; a++)
        #pragma unroll
        for (int b = 0; b < 8; b++)
            #pragma unroll
            for (int c = 0; c < 4; c++) acc[a][b][c] = 0.0f;

    float4 pa[4], pb[4];
    #pragma unroll
    for (int i = 0; i < 4; i++) {
        pa[i] = *(const float4*)(rowp[am + 32 * i][0] + aq * 4);
        pb[i] = *(const float4*)(W + (size_t)(n0 + am + 32 * i) * K + aq * 4);
    }

    for (int kt = 0; kt < K; kt += 32) {
        #pragma unroll
        for (int i = 0; i < 4; i++) {
            int r = am + 32 * i;
            uint4 ta = { f2tf(pa[i].x), f2tf(pa[i].y), f2tf(pa[i].z), f2tf(pa[i].w) };
            uint4 tb = { f2tf(pb[i].x), f2tf(pb[i].y), f2tf(pb[i].z), f2tf(pb[i].w) };
            *(uint4*)&As[r * 32 + swq] = ta;
            *(uint4*)&Bs[r * 32 + swq] = tb;
        }
        __syncthreads();
        int kt2 = kt + 32;
        if (kt2 < K) {
            int seg = kt2 >> 7, off = (kt2 & 127) + aq * 4;
            #pragma unroll
            for (int i = 0; i < 4; i++) {
                pa[i] = *(const float4*)(rowp[am + 32 * i][seg] + off);
                pb[i] = *(const float4*)(W + (size_t)(n0 + am + 32 * i) * K + kt2 + aq * 4);
            }
        }
        #pragma unroll
        for (int ksc = 0; ksc < 8; ksc += 4) {   // two k16 half-tiles
            uint4 alo[2], ahi[2];
            #pragma unroll
            for (int mt = 0; mt < 2; mt++) {
                int rA = wm * 32 + mt * 16 + g;
                int cA = ((ksc + tg) ^ ((rA & 1) << 2)) << 2;
                alo[mt] = *(const uint4*)&As[rA * 32 + cA];
                ahi[mt] = *(const uint4*)&As[(rA + 8) * 32 + cA];
            }
            #pragma unroll
            for (int nt = 0; nt < 8; nt++) {
                int rB = wn * 64 + nt * 8 + g;
                int cB = ((ksc + tg) ^ ((rB & 1) << 2)) << 2;
                uint4 vb = *(const uint4*)&Bs[rB * 32 + cB];
                unsigned b0[2] = { vb.x, vb.y };
                unsigned b1[2] = { vb.z, vb.w };
                #pragma unroll
                for (int mt = 0; mt < 2; mt++) {
                    unsigned a0[4] = { alo[mt].x, ahi[mt].x, alo[mt].y, ahi[mt].y };
                    unsigned a1[4] = { alo[mt].z, ahi[mt].z, alo[mt].w, ahi[mt].w };
                    MMA_TF32(acc[mt][nt], a0, b0);
                    MMA_TF32(acc[mt][nt], a1, b1);
                }
            }
        }
        __syncthreads();
    }

    // ---------------- epilogue ----------------
    #pragma unroll
    for (int mt = 0; mt < 2; mt++) {
        #pragma unroll
        for (int half = 0; half < 2; half++) {
            int mr = wm * 32 + mt * 16 + g + half * 8;
            int mm = m0 + mr;
            bool okm = (mm < M);
            #pragma unroll
            for (int nt = 0; nt < 8; nt++) {
                int nn = n0 + wn * 64 + nt * 8 + 2 * tg;
                float v0 = acc[mt][nt][half * 2 + 0] + bias[nn];
                float v1 = acc[mt][nt][half * 2 + 1] + bias[nn + 1];
                if (mode == 4) {
                    // cols 4h+{0,1}=(i_r,i_z) on even tg; 4h+{2,3}=(i_n,du) on odd
                    int h0 = nn >> 2;
                    float ga = 0.f, gb = 0.f;
                    if (okm) {
                        const float* ghr = g_gh + (size_t)mm * H3;
                        if (!(tg & 1)) { ga = ghr[h0]; gb = ghr[128 + h0]; }
                        else           { ga = ghr[256 + h0]; }
                    }
                    float sg0 = sig_f(v0 + ga);   // even: r
                    float sg1 = sig_f(v1 + gb);   // even: z
                    float rr = __shfl_xor_sync(0xffffffffu, sg0, 1);
                    float zz = __shfl_xor_sync(0xffffffffu, sg1, 1);
                    if ((tg & 1) && okm) {
                        float nval = tanh_f(v0 + rr * ga);
                        float hv = rowp[mr][1][h0];
                        out[(size_t)mm * HH + h0] = (1.0f - zz) * nval + zz * hv;
                    }
                } else if (mode == 0) {
                    if (okm) { float2 o = { v0, v1 }; *(float2*)&out[(size_t)mm * Nout + nn] = o; }
                } else if (mode == 1) {
                    if (okm) {
                        atomicAdd(&g_agg[(size_t)dstIdx[mm] * HH + nn], v0);
                        atomicAdd(&g_agg[(size_t)dstIdx[mm] * HH + nn + 1], v1);
                    }
                } else {
                    if (okm) {
                        float inv = 1.0f / fmaxf(g_deg[mm], 1.0f);
                        float p0 = v0 + g_agg[(size_t)mm * HH + nn] * inv;
                        float p1 = v1 + g_agg[(size_t)mm * HH + nn + 1] * inv;
                        float2 o = { (p0 >= 0.f) ? p0 : RRELU_SLOPE * p0,
                                     (p1 >= 0.f) ? p1 : RRELU_SLOPE * p1 };
                        *(float2*)&out[(size_t)mm * HH + nn] = o;
                    }
                }
            }
        }
    }
}

// ---------------- launch ----------------------------------------------------
extern "C" void kernel_launch(void* const* d_in, const int* in_sizes, int n_in,
                              void* d_out, int out_size) {
    (void)in_sizes; (void)n_in; (void)out_size;
    const float* nf0 = (const float*)d_in[0];
    const float* ef0 = (const float*)d_in[1];
    const int* src = (const int*)d_in[2];
    const int* dst = (const int*)d_in[3];
    const int* et  = (const int*)d_in[4];
    const float* W1  = (const float*)d_in[5];
    const float* b1  = (const float*)d_in[6];
    const float* W2  = (const float*)d_in[7];
    const float* b2  = (const float*)d_in[8];
    const float* W3  = (const float*)d_in[9];
    const float* b3  = (const float*)d_in[10];
    const float* Wih = (const float*)d_in[11];
    const float* Whh = (const float*)d_in[12];
    const float* bih = (const float*)d_in[13];
    const float* bhh = (const float*)d_in[14];
    float* out_nf = (float*)d_out;
    float* out_ef = out_nf + (size_t)NN * HH;

    float *p_nf, *p_ef, *p_ein, *p_emsg, *p_rel, *p_gh, *p_Wg, *p_bg;
    cudaGetSymbolAddress((void**)&p_nf,   g_nf);
    cudaGetSymbolAddress((void**)&p_ef,   g_ef);
    cudaGetSymbolAddress((void**)&p_ein,  g_ein);
    cudaGetSymbolAddress((void**)&p_emsg, g_emsg);
    cudaGetSymbolAddress((void**)&p_rel,  g_rel);
    cudaGetSymbolAddress((void**)&p_gh,   g_gh);
    cudaGetSymbolAddress((void**)&p_Wg,   g_Wg);
    cudaGetSymbolAddress((void**)&p_bg,   g_bg);

    const int TB = 256;
    k_zero_mask_deg<<<((size_t)RR * NN / 4 + TB - 1) / TB, TB>>>();
    k_build<<<(NE + TB - 1) / TB, TB>>>(src, dst, et);
    k_pack<<<(2 * 512 * 128 + TB - 1) / TB, TB>>>(Wih, bih);

    dim3 gE ((NE + 127) / 128, 1);   // E x 128
    dim3 gH ((NE + 127) / 128, 3);   // E x 384 (gh)
    dim3 gF ((NE + 127) / 128, 4);   // E x 512 (fused gi GRU)
    dim3 gN ((NN + 127) / 128, 1);   // N x 128
    dim3 gR (RR, 8);

    for (int l = 0; l < 2; l++) {
        const float* nfi = (l == 0) ? nf0 : p_nf;
        const float* efi = (l == 0) ? ef0 : p_ef;
        float* nfo = (l == 0) ? p_nf : out_nf;
        float* efo = (l == 0) ? p_ef : out_ef;
        const float* W1l  = W1  + (size_t)l * HH * H3;
        const float* b1l  = b1  + (size_t)l * HH;
        const float* W2l  = W2  + (size_t)l * HH * H3;
        const float* b2l  = b2  + (size_t)l * HH;
        const float* W3l  = W3  + (size_t)l * HH * HH;
        const float* b3l  = b3  + (size_t)l * HH;
        const float* Whhl = Whh + (size_t)l * H3 * HH;
        const float* bhhl = bhh + (size_t)l * H3;
        const float* Wgl  = p_Wg + (size_t)l * 512 * 128;
        const float* bgl  = p_bg + (size_t)l * 512;

        k_zero2<<<((size_t)NN * HH + TB - 1) / TB, TB>>>();
        k_rel_part<<<gR, TB>>>(nfi);
        k_rel_fin<<<(RR * HH + TB - 1) / TB, TB>>>();

        // msg = [rel, nf_src, ef] @ W1^T + b1 -> atomic agg
        k_gemm_v4<<<gE, TB>>>(NE, H3, HH, p_rel, et, nfi, src, efi, nullptr,
                              W1l, b1l, nullptr, 1, dst);
        // e_in = [rel, nf_src, nf_dst] @ W2^T + b2
        k_gemm_v4<<<gE, TB>>>(NE, H3, HH, p_rel, et, nfi, src, nfi, dst,
                              W2l, b2l, p_ein, 0, nullptr);
        // gh = ef @ Whh^T + bhh  (shared by both GRUs)
        k_gemm_v4<<<gH, TB>>>(NE, HH, H3, efi, nullptr, nullptr, nullptr, nullptr, nullptr,
                              Whhl, bhhl, p_gh, 0, nullptr);
        // e_msg = GRU(e_in, ef): fused gi GEMM + gh combine
        k_gemm_v4<<<gF, TB>>>(NE, HH, 512, p_ein, nullptr, efi, nullptr, nullptr, nullptr,
                              Wgl, bgl, p_emsg, 4, nullptr);
        // new_ef = GRU(e_msg, ef)
        k_gemm_v4<<<gF, TB>>>(NE, HH, 512, p_emsg, nullptr, efi, nullptr, nullptr, nullptr,
                              Wgl, bgl, efo, 4, nullptr);
        // new_nf = rrelu(agg/deg + nf @ W3^T + b3)
        k_gemm_v4<<<gN, TB>>>(NN, HH, HH, nfi, nullptr, nullptr, nullptr, nullptr, nullptr,
                              W3l, b3l, nfo, 2, nullptr);
    }
}